// round 17
// baseline (speedup 1.0000x reference)
#include <cuda_runtime.h>

#define BATCH 32
#define NPTS  16384
#define GRP   128
#define KNN   64
#define HID   128
#define DIM   384

#define FPS_CTAS    4
#define FPS_THREADS 512
#define FPS_PTS     (NPTS / FPS_CTAS)        // 4096
#define FPS_PPT     (FPS_PTS / FPS_THREADS)  // 8

#define GPB   16          // groups per block in group_kernel
#define PAIRS (GPB / 2)
#define CAP   1024        // compact candidate list capacity per group

// Scratch (no allocations allowed)
__device__ float g_cent[BATCH * GRP * 3];
__device__ float g_hbar[BATCH * GRP * HID];

__device__ __forceinline__ unsigned smem_u32(const void* p) {
    return (unsigned)__cvta_generic_to_shared(p);
}
__device__ __forceinline__ unsigned cluster_rank() {
    unsigned r;
    asm("mov.u32 %0, %%cluster_ctarank;" : "=r"(r));
    return r;
}
__device__ __forceinline__ unsigned mapa_u32(unsigned addr, unsigned rank) {
    unsigned r;
    asm("mapa.shared::cluster.u32 %0, %1, %2;" : "=r"(r) : "r"(addr), "r"(rank));
    return r;
}
__device__ __forceinline__ void mbar_wait_cluster(unsigned addr, unsigned parity) {
    asm volatile(
        "{\n\t"
        ".reg .pred P;\n\t"
        "WL_%=:\n\t"
        "mbarrier.try_wait.parity.acquire.cluster.shared::cta.b64 P, [%0], %1, 0x989680;\n\t"
        "@!P bra WL_%=;\n\t"
        "}" :: "r"(addr), "r"(parity) : "memory");
}

// ---------------------------------------------------------------------------
// Kernel 1: Farthest point sampling, 4-CTA cluster per batch (unchanged R15).
// ---------------------------------------------------------------------------
__global__ __launch_bounds__(FPS_THREADS) __cluster_dims__(FPS_CTAS, 1, 1)
void fps_kernel(const float* __restrict__ pts, float* __restrict__ out_cent) {
    extern __shared__ unsigned char dsm[];
    float* sx = reinterpret_cast<float*>(dsm);       // [4096]
    float* sy = sx + FPS_PTS;
    float* sz = sy + FPS_PTS;
    __shared__ unsigned long long warp_best[16];
    __shared__ unsigned long long cand_pack[2][FPS_CTAS];
    __shared__ float4 cand_xyz[2][FPS_CTAS];
    __shared__ unsigned long long mbar;

    const unsigned rank = cluster_rank();
    const int b = blockIdx.x / FPS_CTAS;
    const int t = threadIdx.x;
    const float* P = pts + (size_t)b * NPTS * 3;
    const int base = (int)rank * FPS_PTS;

    float px[FPS_PPT], py[FPS_PPT], pz[FPS_PPT], dist[FPS_PPT];
#pragma unroll
    for (int j = 0; j < FPS_PPT; j++) {
        int idx = t + j * FPS_THREADS;
        int gi = base + idx;
        px[j] = P[gi * 3 + 0];
        py[j] = P[gi * 3 + 1];
        pz[j] = P[gi * 3 + 2];
        sx[idx] = px[j]; sy[idx] = py[j]; sz[idx] = pz[j];
        dist[j] = 3.4e38f;
    }
    if (t < 16) warp_best[t] = 0ull;
    if (t == 0) {
        unsigned m = smem_u32(&mbar);
        asm volatile("mbarrier.init.shared.b64 [%0], %1;"
                     :: "r"(m), "r"((unsigned)FPS_CTAS) : "memory");
    }
    __syncthreads();
    asm volatile("barrier.cluster.arrive.aligned;" ::: "memory");
    asm volatile("barrier.cluster.wait.aligned;" ::: "memory");

    float cx = P[0], cy = P[1], cz = P[2];

    for (int g = 0; g < GRP; g++) {
        if (rank == 0 && t == 0) {
            size_t o = ((size_t)b * GRP + g) * 3;
            g_cent[o + 0] = cx; g_cent[o + 1] = cy; g_cent[o + 2] = cz;
            if (out_cent) {
                out_cent[o + 0] = cx; out_cent[o + 1] = cy; out_cent[o + 2] = cz;
            }
        }

        float bv = -1.0f;
        int bi = 0;
#pragma unroll
        for (int j = 0; j < FPS_PPT; j++) {
            float dx = px[j] - cx;
            float dy = py[j] - cy;
            float dz = pz[j] - cz;
            float d = dx * dx + dy * dy + dz * dz;
            float nd = fminf(dist[j], d);
            dist[j] = nd;
            if (nd > bv) { bv = nd; bi = base + t + j * FPS_THREADS; }
        }
        unsigned long long pack =
            ((unsigned long long)__float_as_uint(bv) << 32) |
            (unsigned long long)(0xFFFFFFFFu - (unsigned)bi);
        atomicMax(&warp_best[t >> 5], pack);
        __syncthreads();

        if (t < 32) {
            unsigned long long v = (t < 16) ? warp_best[t] : 0ull;
            if (t < 16) warp_best[t] = 0ull;
            __syncwarp();
#pragma unroll
            for (int off = 8; off; off >>= 1) {
                unsigned long long ov = __shfl_down_sync(0xffffffffu, v, off);
                if (ov > v) v = ov;
            }
            if (t == 0) {
                int gi = (int)(0xFFFFFFFFu - (unsigned)(v & 0xFFFFFFFFull));
                int li = gi - base;
                float fx = sx[li], fy = sy[li], fz = sz[li];
                unsigned buf = (unsigned)(g & 1);
                unsigned lp = smem_u32(&cand_pack[buf][rank]);
                unsigned lx = smem_u32(&cand_xyz[buf][rank]);
                unsigned lm = smem_u32(&mbar);
#pragma unroll
                for (unsigned r = 0; r < FPS_CTAS; r++) {
                    unsigned rp = mapa_u32(lp, r);
                    unsigned rx = mapa_u32(lx, r);
                    unsigned rm = mapa_u32(lm, r);
                    asm volatile("st.shared::cluster.u64 [%0], %1;"
                                 :: "r"(rp), "l"(v) : "memory");
                    asm volatile("st.shared::cluster.v4.f32 [%0], {%1, %2, %3, %4};"
                                 :: "r"(rx), "f"(fx), "f"(fy), "f"(fz), "f"(0.0f)
                                 : "memory");
                    asm volatile(
                        "mbarrier.arrive.release.cluster.shared::cluster.b64 _, [%0];"
                        :: "r"(rm) : "memory");
                }
            }
        }

        mbar_wait_cluster(smem_u32(&mbar), (unsigned)(g & 1));
        {
            unsigned buf = (unsigned)(g & 1);
            unsigned long long best = cand_pack[buf][0];
            int br = 0;
#pragma unroll
            for (int r = 1; r < FPS_CTAS; r++) {
                unsigned long long c = cand_pack[buf][r];
                if (c > best) { best = c; br = r; }
            }
            float4 w = cand_xyz[buf][br];
            cx = w.x; cy = w.y; cz = w.z;
        }
    }

    asm volatile("barrier.cluster.arrive.aligned;" ::: "memory");
    asm volatile("barrier.cluster.wait.aligned;" ::: "memory");
}

// ---------------------------------------------------------------------------
// group_kernel helpers
// ---------------------------------------------------------------------------
__device__ __forceinline__ unsigned ord_key(float f) {
    unsigned u = __float_as_uint(f);
    return (u & 0x80000000u) ? ~u : (u | 0x80000000u);
}
__device__ __forceinline__ void hbar(int h) {
    asm volatile("bar.sync %0, 256;" :: "r"(h + 1) : "memory");
}

// 256-thread (half-block) 256-bin cumulative search using named barrier h+1.
__device__ __forceinline__ void half_select(unsigned* histH, unsigned* wsumH,
                                            unsigned* s_pre, int* s_kk,
                                            unsigned prefix, int k, int shift,
                                            int th, int h) {
    const int lane = th & 31;
    unsigned c = histH[th];
    unsigned x = c;
#pragma unroll
    for (int off = 1; off < 32; off <<= 1) {
        unsigned y = __shfl_up_sync(0xffffffffu, x, off);
        if (lane >= off) x += y;
    }
    if (lane == 31) wsumH[th >> 5] = x;
    hbar(h);
    if (th < 8) {
        unsigned v = wsumH[th];
        unsigned xx = v;
#pragma unroll
        for (int off = 1; off < 8; off <<= 1) {
            unsigned y = __shfl_up_sync(0x000000ffu, xx, off);
            if (th >= off) xx += y;
        }
        wsumH[th] = xx - v;  // exclusive
    }
    hbar(h);
    unsigned incl = x + wsumH[th >> 5];
    unsigned excl = incl - c;
    if (excl < (unsigned)k && incl >= (unsigned)k) {
        *s_pre = prefix | ((unsigned)th << shift);
        *s_kk = k - (int)excl;
    }
    hbar(h);
}

// ---------------------------------------------------------------------------
// Kernel 2: 16 groups per block, batch points cached SoA in SMEM.
// Per pair of groups: round-1 histogram (shared point loads + shared p2),
// route pass (top<b1 -> sel, top==b1 -> compact list), then per-256-thread
// half: radix rounds 2-4 + final selection on the compact list only
// (full-scan fallback if the list overflows CAP), then fused gelu-MLP mean.
// Selection math identical to reference (same key, exact threshold, stable
// lowest-index ties).
// ---------------------------------------------------------------------------
__global__ __launch_bounds__(512) void group_kernel(const float* __restrict__ pts,
                                                    const float* __restrict__ w1,
                                                    const float* __restrict__ b1v) {
    extern __shared__ float sp[];
    float* spx = sp;                 // [NPTS]
    float* spy = sp + NPTS;
    float* spz = sp + 2 * NPTS;

    __shared__ unsigned hist[2][256];
    __shared__ unsigned wsum[2][8];
    __shared__ unsigned s_pre[2];
    __shared__ int s_kk[2];
    __shared__ unsigned cl_key[2][CAP];
    __shared__ int cl_idx[2][CAP];
    __shared__ int sel[2][KNN];
    __shared__ int eql[2][KNN];
    __shared__ int s_nless[2], s_m[2], s_neq[2];
    __shared__ float loc[2][KNN][3];
    __shared__ float hpart[2][256];

    const int b = blockIdx.y;
    const int gbase = blockIdx.x * GPB;
    const int t = threadIdx.x;
    const int h = t >> 8;       // half id (0/1)
    const int th = t & 255;
    const int lane = t & 31;
    const float* P = pts + (size_t)b * NPTS * 3;

    // Load batch points SoA into SMEM (vectorized).
    {
        const float4* P4 = reinterpret_cast<const float4*>(P);
        float4* X4 = reinterpret_cast<float4*>(spx);
        float4* Y4 = reinterpret_cast<float4*>(spy);
        float4* Z4 = reinterpret_cast<float4*>(spz);
        for (int c = t; c < NPTS / 4; c += 512) {
            float4 a = P4[3 * c + 0];
            float4 q = P4[3 * c + 1];
            float4 r = P4[3 * c + 2];
            X4[c] = make_float4(a.x, a.w, q.z, r.y);
            Y4[c] = make_float4(a.y, q.x, q.w, r.z);
            Z4[c] = make_float4(a.z, q.y, r.x, r.w);
        }
    }
    __syncthreads();

    const float4* X4 = reinterpret_cast<const float4*>(spx);
    const float4* Y4 = reinterpret_cast<const float4*>(spy);
    const float4* Z4 = reinterpret_cast<const float4*>(spz);

    for (int pr = 0; pr < PAIRS; pr++) {
        const int g0 = gbase + 2 * pr;
        const float* C0 = g_cent + ((size_t)b * GRP + g0) * 3;
        const float* C1 = C0 + 3;
        const float c0x = C0[0], c0y = C0[1], c0z = C0[2];
        const float c1x = C1[0], c1y = C1[1], c1z = C1[2];
        const float c0s = c0x * c0x + c0y * c0y + c0z * c0z;
        const float c1s = c1x * c1x + c1y * c1y + c1z * c1z;

        if (t < 256) hist[0][t] = 0; else hist[1][t & 255] = 0;
        if (t == 0) {
            s_nless[0] = 0; s_nless[1] = 0;
            s_m[0] = 0; s_m[1] = 0;
            s_neq[0] = 0; s_neq[1] = 0;
        }
        __syncthreads();

        // Pass A: round-1 histograms for both groups (match_any-aggregated).
        for (int c = t; c < NPTS / 4; c += 512) {
            float4 xv = X4[c], yv = Y4[c], zv = Z4[c];
            float xs[4] = {xv.x, xv.y, xv.z, xv.w};
            float ys[4] = {yv.x, yv.y, yv.z, yv.w};
            float zs[4] = {zv.x, zv.y, zv.z, zv.w};
#pragma unroll
            for (int e = 0; e < 4; e++) {
                float p2 = xs[e] * xs[e] + ys[e] * ys[e] + zs[e] * zs[e];
                float d0 = c0x * xs[e] + c0y * ys[e] + c0z * zs[e];
                float d1 = c1x * xs[e] + c1y * ys[e] + c1z * zs[e];
                unsigned k0 = ord_key((c0s + p2) - 2.0f * d0);
                unsigned k1 = ord_key((c1s + p2) - 2.0f * d1);
                unsigned b0 = k0 >> 24;
                unsigned pe0 = __match_any_sync(0xffffffffu, b0);
                if (lane == __ffs(pe0) - 1)
                    atomicAdd(&hist[0][b0], (unsigned)__popc(pe0));
                unsigned bq = k1 >> 24;
                unsigned pe1 = __match_any_sync(0xffffffffu, bq);
                if (lane == __ffs(pe1) - 1)
                    atomicAdd(&hist[1][bq], (unsigned)__popc(pe1));
            }
        }
        __syncthreads();

        // Round-1 bin selection, one group per half.
        half_select(hist[h], wsum[h], &s_pre[h], &s_kk[h], 0u, KNN, 24, th, h);
        __syncthreads();

        const unsigned pre0 = s_pre[0];
        const unsigned pre1 = s_pre[1];

        // Pass B: route. top<b1 -> sel directly (<=63), top==b1 -> compact.
        for (int c = t; c < NPTS / 4; c += 512) {
            float4 xv = X4[c], yv = Y4[c], zv = Z4[c];
            float xs[4] = {xv.x, xv.y, xv.z, xv.w};
            float ys[4] = {yv.x, yv.y, yv.z, yv.w};
            float zs[4] = {zv.x, zv.y, zv.z, zv.w};
#pragma unroll
            for (int e = 0; e < 4; e++) {
                int i = 4 * c + e;
                float p2 = xs[e] * xs[e] + ys[e] * ys[e] + zs[e] * zs[e];
                float d0 = c0x * xs[e] + c0y * ys[e] + c0z * zs[e];
                float d1 = c1x * xs[e] + c1y * ys[e] + c1z * zs[e];
                unsigned k0 = ord_key((c0s + p2) - 2.0f * d0);
                unsigned k1 = ord_key((c1s + p2) - 2.0f * d1);
                if (k0 < pre0) {
                    int p = atomicAdd(&s_nless[0], 1);
                    sel[0][p] = i;
                } else if ((k0 & 0xFF000000u) == pre0) {
                    int p = atomicAdd(&s_m[0], 1);
                    if (p < CAP) { cl_key[0][p] = k0; cl_idx[0][p] = i; }
                }
                if (k1 < pre1) {
                    int p = atomicAdd(&s_nless[1], 1);
                    sel[1][p] = i;
                } else if ((k1 & 0xFF000000u) == pre1) {
                    int p = atomicAdd(&s_m[1], 1);
                    if (p < CAP) { cl_key[1][p] = k1; cl_idx[1][p] = i; }
                }
            }
        }
        __syncthreads();

        // -------- per-half: rounds 2-4 + final selection --------
        {
            const float chx = h ? c1x : c0x;
            const float chy = h ? c1y : c0y;
            const float chz = h ? c1z : c0z;
            const float chs = h ? c1s : c0s;
            const unsigned pre_r1 = s_pre[h];
            unsigned prefix = pre_r1;
            int k = s_kk[h];
            const int m = s_m[h];

            if (m <= CAP) {
#pragma unroll
                for (int shift = 16; shift >= 0; shift -= 8) {
                    hist[h][th] = 0;
                    hbar(h);
                    const unsigned hmask = 0xFFFFFFFFu << (shift + 8);
                    for (int i = th; i < m; i += 256) {
                        unsigned key = cl_key[h][i];
                        if ((key & hmask) == prefix)
                            atomicAdd(&hist[h][(key >> shift) & 255u], 1u);
                    }
                    hbar(h);
                    half_select(hist[h], wsum[h], &s_pre[h], &s_kk[h],
                                prefix, k, shift, th, h);
                    prefix = s_pre[h];
                    k = s_kk[h];
                }
                const unsigned T = prefix;
                for (int i = th; i < m; i += 256) {
                    unsigned key = cl_key[h][i];
                    if (key < T) {
                        int p = atomicAdd(&s_nless[h], 1);
                        sel[h][p] = cl_idx[h][i];
                    } else if (key == T) {
                        int p = atomicAdd(&s_neq[h], 1);
                        if (p < KNN) eql[h][p] = cl_idx[h][i];
                    }
                }
                hbar(h);
            } else {
                // Fallback: full scans restricted to round-1 prefix.
#pragma unroll
                for (int shift = 16; shift >= 0; shift -= 8) {
                    hist[h][th] = 0;
                    hbar(h);
                    const unsigned hmask = 0xFFFFFFFFu << (shift + 8);
                    for (int i = th; i < NPTS; i += 256) {
                        float x = spx[i], y = spy[i], z = spz[i];
                        float p2 = x * x + y * y + z * z;
                        float dot = chx * x + chy * y + chz * z;
                        unsigned key = ord_key((chs + p2) - 2.0f * dot);
                        if ((key & hmask) == prefix)
                            atomicAdd(&hist[h][(key >> shift) & 255u], 1u);
                    }
                    hbar(h);
                    half_select(hist[h], wsum[h], &s_pre[h], &s_kk[h],
                                prefix, k, shift, th, h);
                    prefix = s_pre[h];
                    k = s_kk[h];
                }
                const unsigned T = prefix;
                for (int i = th; i < NPTS; i += 256) {
                    float x = spx[i], y = spy[i], z = spz[i];
                    float p2 = x * x + y * y + z * z;
                    float dot = chx * x + chy * y + chz * z;
                    unsigned key = ord_key((chs + p2) - 2.0f * dot);
                    if ((key & 0xFF000000u) == pre_r1) {
                        if (key < T) {
                            int p = atomicAdd(&s_nless[h], 1);
                            sel[h][p] = i;
                        } else if (key == T) {
                            int p = atomicAdd(&s_neq[h], 1);
                            if (p < KNN) eql[h][p] = i;
                        }
                    }
                }
                hbar(h);
            }

            if (th == 0) {
                int nless = s_nless[h];
                int need = KNN - nless;
                int mm = (s_neq[h] < KNN) ? s_neq[h] : KNN;
                for (int a = 1; a < mm; a++) {  // tiny insertion sort
                    int v = eql[h][a];
                    int c = a - 1;
                    while (c >= 0 && eql[h][c] > v) { eql[h][c + 1] = eql[h][c]; c--; }
                    eql[h][c + 1] = v;
                }
                for (int a = 0; a < need; a++) sel[h][nless + a] = eql[h][a];
            }
            hbar(h);

            if (th < KNN) {
                int idx = sel[h][th];
                loc[h][th][0] = spx[idx] - chx;
                loc[h][th][1] = spy[idx] - chy;
                loc[h][th][2] = spz[idx] - chz;
            }
            hbar(h);

            // gelu-MLP layer1 + mean over 64 neighbors; 256 threads/group.
            const int j = th & 127;
            const float wx = w1[j], wy = w1[HID + j], wz = w1[2 * HID + j];
            const float bb = b1v[j];
            float acc = 0.0f;
            const int kk0 = (th >> 7) * 32;
#pragma unroll
            for (int kk = 0; kk < 32; kk++) {
                int kp = kk0 + kk;
                float v = loc[h][kp][0] * wx + loc[h][kp][1] * wy +
                          loc[h][kp][2] * wz + bb;
                float hv = 0.5f * v * (1.0f + erff(v * 0.7071067811865476f));
                acc += hv;
            }
            hpart[h][th] = acc;
            hbar(h);
            if (th < HID)
                g_hbar[((size_t)b * GRP + g0 + h) * HID + th] =
                    (hpart[h][th] + hpart[h][th + 128]) * (1.0f / (float)KNN);
        }
        __syncthreads();  // hist/counters reused next pair
    }
}

// ---------------------------------------------------------------------------
// Kernel 3: tokens = hbar @ w2 + b2 (4096x384x128 GEMM), then LayerNorm.
// ---------------------------------------------------------------------------
__global__ __launch_bounds__(384) void head_kernel(const float* __restrict__ w2,
                                                   const float* __restrict__ b2,
                                                   const float* __restrict__ gamma,
                                                   const float* __restrict__ beta,
                                                   float* __restrict__ out_tok) {
    __shared__ float sh[16 * HID];
    __shared__ float tok[16][DIM];

    const int row0 = blockIdx.x * 16;
    const int t = threadIdx.x;

    for (int i = t; i < 16 * HID; i += 384)
        sh[i] = g_hbar[(size_t)row0 * HID + i];
    __syncthreads();

    float acc[16];
#pragma unroll
    for (int r = 0; r < 16; r++) acc[r] = 0.0f;

    for (int jj = 0; jj < HID; jj++) {
        float w = w2[jj * DIM + t];
#pragma unroll
        for (int r = 0; r < 16; r++) acc[r] += sh[r * HID + jj] * w;
    }
    const float bd = b2[t];
#pragma unroll
    for (int r = 0; r < 16; r++) tok[r][t] = acc[r] + bd;
    __syncthreads();

    const int w = t >> 5, lane = t & 31;
    for (int r = w; r < 16; r += 12) {
        float s = 0.0f;
        for (int c = lane; c < DIM; c += 32) s += tok[r][c];
#pragma unroll
        for (int off = 16; off; off >>= 1) s += __shfl_xor_sync(0xffffffffu, s, off);
        float mu = s * (1.0f / DIM);
        float v = 0.0f;
        for (int c = lane; c < DIM; c += 32) {
            float d0 = tok[r][c] - mu;
            v += d0 * d0;
        }
#pragma unroll
        for (int off = 16; off; off >>= 1) v += __shfl_xor_sync(0xffffffffu, v, off);
        float rstd = rsqrtf(v * (1.0f / DIM) + 1e-5f);
        for (int c = lane; c < DIM; c += 32)
            out_tok[((size_t)row0 + r) * DIM + c] =
                (tok[r][c] - mu) * rstd * gamma[c] + beta[c];
    }
}

// ---------------------------------------------------------------------------
extern "C" void kernel_launch(void* const* d_in, const int* in_sizes, int n_in,
                              void* d_out, int out_size) {
    const float* pts   = (const float*)d_in[0];  // [32,16384,3]
    const float* w1    = (const float*)d_in[1];  // [3,128]
    const float* b1    = (const float*)d_in[2];  // [128]
    const float* w2    = (const float*)d_in[3];  // [128,384]
    const float* b2    = (const float*)d_in[4];  // [384]
    const float* gamma = (const float*)d_in[5];  // [384]
    const float* beta  = (const float*)d_in[6];  // [384]

    float* out = (float*)d_out;
    float* out_cent = nullptr;
    float* out_tok = out;
    if (out_size == BATCH * GRP * (3 + DIM)) {
        out_cent = out;
        out_tok = out + BATCH * GRP * 3;
    }

    cudaFuncSetAttribute(fps_kernel, cudaFuncAttributeMaxDynamicSharedMemorySize,
                         3 * FPS_PTS * (int)sizeof(float));
    cudaFuncSetAttribute(group_kernel, cudaFuncAttributeMaxDynamicSharedMemorySize,
                         3 * NPTS * (int)sizeof(float));

    fps_kernel<<<BATCH * FPS_CTAS, FPS_THREADS, 3 * FPS_PTS * sizeof(float)>>>(pts, out_cent);
    group_kernel<<<dim3(GRP / GPB, BATCH), 512, 3 * NPTS * sizeof(float)>>>(pts, w1, b1);
    head_kernel<<<(BATCH * GRP) / 16, 384>>>(w2, b2, gamma, beta, out_tok);
}